// round 1
// baseline (speedup 1.0000x reference)
#include <cuda_runtime.h>
#include <cuda_bf16.h>
#include <cstdint>

// Problem constants (fixed by setup_inputs)
#define BSZ 256
#define SEQ 64
#define EMB 1024
#define HID 512
#define MAXN 127           // 2*S-1
#define NSTEP 63           // S-1
#define NCAT 511

typedef unsigned long long ull;

// ---------------- f32x2 helpers (FFMA2 path: 2x fp32 throughput on sm_103a) ----
__device__ __forceinline__ ull pack2(float lo, float hi) {
    ull r; asm("mov.b64 %0,{%1,%2};" : "=l"(r) : "f"(lo), "f"(hi)); return r;
}
__device__ __forceinline__ void unpack2(ull v, float &lo, float &hi) {
    asm("mov.b64 {%0,%1},%2;" : "=f"(lo), "=f"(hi) : "l"(v));
}
__device__ __forceinline__ void fma2(ull &d, ull a, ull b) {
    asm("fma.rn.f32x2 %0, %1, %2, %0;" : "+l"(d) : "l"(a), "l"(b));
}

// ---------------- scratch (device globals: allocation-free) -------------------
__device__ float g_comb[(size_t)BSZ * SEQ * HID];        // 33.5 MB  relu(GEMM1)
__device__ float g_nodes[(size_t)BSZ * MAXN * HID];      // 66.6 MB  node vectors

// ==============================================================================
// GEMM1: comb[m,n] = relu( sum_{k<512} X[m,k]W1[k,n] + sum_{k>=512} X[m,k]W2[k-512,n] )
// M=16384, N=512, K=1024.  BM=128, BN=64, BK=16, 256 thr, thread tile 8x4, f32x2.
// ==============================================================================
#define G_BM 128
#define G_BN 64
#define G_BK 16
#define SSTR 18   // smem row stride (even -> 8B aligned float2 reads, spread banks)

__global__ __launch_bounds__(256, 2) void gemm1_kernel(
    const float* __restrict__ X, const float* __restrict__ W1, const float* __restrict__ W2)
{
    __shared__ __align__(16) float As[G_BM * SSTR];
    __shared__ __align__(16) float Bs[G_BN * SSTR];

    const int tid  = threadIdx.x;
    const int warp = tid >> 5, lane = tid & 31;
    const int tmBase = (warp >> 1) * 32 + (lane >> 3);  // rows: tmBase + 4*i, i<8
    const int tnBase = (warp & 1) * 32 + (lane & 7);    // cols: tnBase + 8*j, j<4
    const int m0 = blockIdx.x * G_BM;
    const int n0 = blockIdx.y * G_BN;

    const int aRow = tid >> 1;
    const int aK   = (tid & 1) * 8;
    const int bK   = tid >> 4;        // 0..15
    const int bN   = (tid & 15) * 4;  // 0..60

    ull acc[8][4];
#pragma unroll
    for (int i = 0; i < 8; i++)
#pragma unroll
        for (int j = 0; j < 4; j++) acc[i][j] = 0ull;

    const float* aG = X + (size_t)(m0 + aRow) * EMB + aK;

    for (int kt = 0; kt < EMB; kt += G_BK) {
        float4 av0 = *(const float4*)(aG + kt);
        float4 av1 = *(const float4*)(aG + kt + 4);
        int kk = kt + bK;
        const float* wp = (kk < HID) ? (W1 + (size_t)kk * HID + (n0 + bN))
                                     : (W2 + (size_t)(kk - HID) * HID + (n0 + bN));
        float4 bv = *(const float4*)wp;

        __syncthreads();
        float* as = &As[aRow * SSTR + aK];
        as[0]=av0.x; as[1]=av0.y; as[2]=av0.z; as[3]=av0.w;
        as[4]=av1.x; as[5]=av1.y; as[6]=av1.z; as[7]=av1.w;
        Bs[(bN+0)*SSTR + bK] = bv.x;
        Bs[(bN+1)*SSTR + bK] = bv.y;
        Bs[(bN+2)*SSTR + bK] = bv.z;
        Bs[(bN+3)*SSTR + bK] = bv.w;
        __syncthreads();

#pragma unroll
        for (int kp = 0; kp < G_BK; kp += 2) {
            ull af[8], bf[4];
#pragma unroll
            for (int i = 0; i < 8; i++)
                af[i] = *(const ull*)&As[(tmBase + i*4) * SSTR + kp];
#pragma unroll
            for (int j = 0; j < 4; j++)
                bf[j] = *(const ull*)&Bs[(tnBase + j*8) * SSTR + kp];
#pragma unroll
            for (int i = 0; i < 8; i++)
#pragma unroll
                for (int j = 0; j < 4; j++)
                    fma2(acc[i][j], af[i], bf[j]);
        }
    }

#pragma unroll
    for (int i = 0; i < 8; i++) {
        float* cp = g_comb + (size_t)(m0 + tmBase + i*4) * HID + n0;
#pragma unroll
        for (int j = 0; j < 4; j++) {
            float lo, hi; unpack2(acc[i][j], lo, hi);
            float v = lo + hi;
            cp[tnBase + j*8] = v > 0.f ? v : 0.f;
        }
    }
}

// ==============================================================================
// Normalize rows of comb and scatter into g_nodes per original_pos.
// One block per (b,s) row. 128 threads, float4 each.
// ==============================================================================
__global__ __launch_bounds__(128) void normalize_scatter_kernel(const int* __restrict__ opos)
{
    const int row = blockIdx.x;          // 0..16383
    const int b = row >> 6;
    const int dst = opos[(row << 1) + 0];
    const int src = opos[(row << 1) + 1];
    const int tid = threadIdx.x;

    const float4* cp = (const float4*)(g_comb + ((size_t)(b * SEQ + src)) * HID);
    float4 v = cp[tid];
    float ss = v.x*v.x + v.y*v.y + v.z*v.z + v.w*v.w;
#pragma unroll
    for (int o = 16; o; o >>= 1) ss += __shfl_xor_sync(0xffffffffu, ss, o);
    __shared__ float ws[4];
    if ((tid & 31) == 0) ws[tid >> 5] = ss;
    __syncthreads();
    float tot = ws[0] + ws[1] + ws[2] + ws[3];
    float sc = 1.f / (sqrtf(tot) + 1e-6f);
    float4 o4 = make_float4(v.x*sc, v.y*sc, v.z*sc, v.w*sc);
    ((float4*)(g_nodes + ((size_t)(b * MAXN + dst)) * HID))[tid] = o4;
}

// ==============================================================================
// Chain: one block per batch, 63 sequential circular-correlation steps.
// c[n] = sum_j L[j] * R[(j+n) mod 512], then L2-normalize, write node p.
// 128 threads, 4 consecutive outputs each, f32x2 pairwise-j accumulation,
// R duplicated (1024) in smem to eliminate the modulo, sliding register window.
// ==============================================================================
__global__ __launch_bounds__(128) void chain_kernel(const int* __restrict__ cinfo)
{
    const int b = blockIdx.x;
    const int tid = threadIdx.x;
    __shared__ __align__(16) float sL[512];
    __shared__ __align__(16) float sR2[1024];
    __shared__ float ws[4];

    float* nb = g_nodes + (size_t)b * MAXN * HID;
    const int* info = cinfo + (size_t)b * NSTEP * 4;
    const int n0 = tid * 4;

    for (int k = 0; k < NSTEP; k++) {
        const int t = info[k*4 + 0];
        const int p = info[k*4 + 1];
        const int l = info[k*4 + 2];
        const int r = info[k*4 + 3];

        __syncthreads();  // prior writes visible; smem free to overwrite
        float4 lv = ((const float4*)(nb + (size_t)l * HID))[tid];
        float4 rv = ((const float4*)(nb + (size_t)r * HID))[tid];
        ((float4*)sL)[tid] = lv;
        ((float4*)sR2)[tid] = rv;
        ((float4*)sR2)[tid + 128] = rv;
        __syncthreads();

        if (t == 2) {
            ull a0 = 0ull, a1 = 0ull, a2 = 0ull, a3 = 0ull;
            float w0 = sR2[n0], w1 = sR2[n0 + 1], w2 = sR2[n0 + 2];
#pragma unroll 8
            for (int j = 0; j < 512; j += 2) {
                float w3 = sR2[n0 + j + 3];
                float w4 = sR2[n0 + j + 4];
                ull aa = *(const ull*)&sL[j];
                fma2(a0, aa, pack2(w0, w1));
                fma2(a1, aa, pack2(w1, w2));
                fma2(a2, aa, pack2(w2, w3));
                fma2(a3, aa, pack2(w3, w4));
                w0 = w2; w1 = w3; w2 = w4;
            }
            float lo, hi, c0, c1, c2, c3;
            unpack2(a0, lo, hi); c0 = lo + hi;
            unpack2(a1, lo, hi); c1 = lo + hi;
            unpack2(a2, lo, hi); c2 = lo + hi;
            unpack2(a3, lo, hi); c3 = lo + hi;

            float ss = c0*c0 + c1*c1 + c2*c2 + c3*c3;
#pragma unroll
            for (int o = 16; o; o >>= 1) ss += __shfl_xor_sync(0xffffffffu, ss, o);
            if ((tid & 31) == 0) ws[tid >> 5] = ss;
            __syncthreads();
            float sc = 1.f / (sqrtf(ws[0] + ws[1] + ws[2] + ws[3]) + 1e-6f);
            float4 o4 = make_float4(c0*sc, c1*sc, c2*sc, c3*sc);
            ((float4*)(nb + (size_t)p * HID))[tid] = o4;
        } else if (t == 1) {
            ((float4*)(nb + (size_t)p * HID))[tid] = lv;
        }
        // t == other: node p keeps its current value (no write)
    }
}

// ==============================================================================
// GEMM2: out[m,n] = sum_k nodes[m,k] * LW[n,k] + LB[n]   (NT, both K-contiguous)
// M = 32512 (=256*127), N = 511, K = 512.
// ==============================================================================
__global__ __launch_bounds__(256, 2) void gemm2_kernel(
    const float* __restrict__ LW, const float* __restrict__ LB, float* __restrict__ out)
{
    __shared__ __align__(16) float As[G_BM * SSTR];
    __shared__ __align__(16) float Bs[G_BN * SSTR];

    const int tid  = threadIdx.x;
    const int warp = tid >> 5, lane = tid & 31;
    const int tmBase = (warp >> 1) * 32 + (lane >> 3);
    const int tnBase = (warp & 1) * 32 + (lane & 7);
    const int m0 = blockIdx.x * G_BM;
    const int n0 = blockIdx.y * G_BN;

    const int aRow = tid >> 1;
    const int aK   = (tid & 1) * 8;
    const int bRow = tid >> 2;        // 0..63 (n within tile)
    const int bK4  = (tid & 3) * 4;   // 0..12

    ull acc[8][4];
#pragma unroll
    for (int i = 0; i < 8; i++)
#pragma unroll
        for (int j = 0; j < 4; j++) acc[i][j] = 0ull;

    const float* aG = g_nodes + (size_t)(m0 + aRow) * HID + aK;
    const int nIdx = n0 + bRow;
    const bool bValid = (nIdx < NCAT);

    for (int kt = 0; kt < HID; kt += G_BK) {
        float4 av0 = *(const float4*)(aG + kt);
        float4 av1 = *(const float4*)(aG + kt + 4);
        float4 bv = make_float4(0.f, 0.f, 0.f, 0.f);
        if (bValid) bv = *(const float4*)(LW + (size_t)nIdx * HID + kt + bK4);

        __syncthreads();
        float* as = &As[aRow * SSTR + aK];
        as[0]=av0.x; as[1]=av0.y; as[2]=av0.z; as[3]=av0.w;
        as[4]=av1.x; as[5]=av1.y; as[6]=av1.z; as[7]=av1.w;
        float* bs = &Bs[bRow * SSTR + bK4];
        bs[0]=bv.x; bs[1]=bv.y; bs[2]=bv.z; bs[3]=bv.w;
        __syncthreads();

#pragma unroll
        for (int kp = 0; kp < G_BK; kp += 2) {
            ull af[8], bf[4];
#pragma unroll
            for (int i = 0; i < 8; i++)
                af[i] = *(const ull*)&As[(tmBase + i*4) * SSTR + kp];
#pragma unroll
            for (int j = 0; j < 4; j++)
                bf[j] = *(const ull*)&Bs[(tnBase + j*8) * SSTR + kp];
#pragma unroll
            for (int i = 0; i < 8; i++)
#pragma unroll
                for (int j = 0; j < 4; j++)
                    fma2(acc[i][j], af[i], bf[j]);
        }
    }

#pragma unroll
    for (int i = 0; i < 8; i++) {
        float* cp = out + (size_t)(m0 + tmBase + i*4) * NCAT;
#pragma unroll
        for (int j = 0; j < 4; j++) {
            int n = n0 + tnBase + j*8;
            if (n < NCAT) {
                float lo, hi; unpack2(acc[i][j], lo, hi);
                cp[n] = lo + hi + LB[n];
            }
        }
    }
}

// ==============================================================================
extern "C" void kernel_launch(void* const* d_in, const int* in_sizes, int n_in,
                              void* d_out, int out_size)
{
    const float* seq  = (const float*)d_in[0];   // (256,64,1024)
    const float* W1   = (const float*)d_in[1];   // (512,512)
    const float* W2   = (const float*)d_in[2];   // (512,512)
    const float* LW   = (const float*)d_in[3];   // (511,512)
    const float* LB   = (const float*)d_in[4];   // (511,)
    const int*   opos = (const int*)d_in[7];     // (256,64,2)
    const int*   cinf = (const int*)d_in[8];     // (256,63,4)
    float* out = (float*)d_out;                  // (256,127,511)

    dim3 g1(BSZ * SEQ / G_BM, HID / G_BN);       // 128 x 8
    gemm1_kernel<<<g1, 256>>>(seq, W1, W2);

    normalize_scatter_kernel<<<BSZ * SEQ, 128>>>(opos);

    chain_kernel<<<BSZ, 128>>>(cinf);

    dim3 g2(BSZ * MAXN / G_BM, (NCAT + G_BN - 1) / G_BN);  // 254 x 8
    gemm2_kernel<<<g2, 256>>>(LW, LB, out);
}